// round 14
// baseline (speedup 1.0000x reference)
#include <cuda_runtime.h>

#define NB   16
#define FW   512
#define SW   128
#define IMG  (SW*SW)        // 16384
#define NPIX (NB*IMG)       // 262144
#define CSTR 141            // s_curr stride (scalar conflict-free)
#define PSTR 132            // s_prev stride (float4 conflict-free, 4i pattern)
#define TSTR 148            // hsumT stride (37 quads/col, gcd(5,8)=1 -> quad conflict-free)

// ---------------- device scratch (no cudaMalloc allowed) ----------------
__device__ float g_pblur[2*NPIX];
__device__ float g_rain [NPIX];
__device__ unsigned g_best[NPIX];    // packed (costbits & ~0xFF) | shiftIdx
__device__ float g_flowb[2*NPIX];
__device__ float g_partial[4096];
__device__ unsigned g_done;          // zero-init; reset by last block each run

__constant__ float GW[7] = {0.0044330482f, 0.0540055826f, 0.2420362293f,
                            0.3990502800f,
                            0.2420362293f, 0.0540055826f, 0.0044330482f};

// ---- K0: fused log1p-downsample + 7x7 blur (strip) + rain + best-init ----
__global__ void __launch_bounds__(256) k_blurPrep(const float* __restrict__ target,
                                                  const float* __restrict__ ref) {
    __shared__ float s_in[38 * 128];
    __shared__ float s_h [38 * 128];
    int img  = blockIdx.x >> 2;
    int s    = blockIdx.x & 3;
    int rbase = 32 * s - 3;
    int b    = img & 15;
    bool isT = (img >= 16);
    const float* src = (isT ? target : ref) + b * (FW * FW);
    float* out = g_pblur + img * IMG + 32 * s * 128;

    for (int i = threadIdx.x; i < 38 * 128; i += 256) {
        int lr = i >> 7, x = i & 127;
        int gr = min(max(rbase + lr, 0), 127);
        int o = (4 * gr + 1) * FW + (4 * x + 1);
        float a0 = src[o], a1 = src[o + 1], a2 = src[o + FW], a3 = src[o + FW + 1];
        s_in[i] = 0.25f * (log1pf(fmaxf(a0, 0.f)) + log1pf(fmaxf(a1, 0.f)) +
                           log1pf(fmaxf(a2, 0.f)) + log1pf(fmaxf(a3, 0.f)));
        if (lr >= 3 && lr < 35) {
            int gi = b * IMG + (gr << 7) + x;
            if (isT) {
                float tm = 0.25f * (a0 + a1 + a2 + a3);
                g_rain[gi] = (tm >= 0.1f) ? 1.0f : 0.0f;
            } else {
                g_best[gi] = 0xFFFFFFFFu;
            }
        }
    }
    __syncthreads();
    for (int i = threadIdx.x; i < 38 * 128; i += 256) {
        int x = i & 127;
        int lr7 = i - x;
        float a = 0.f;
        #pragma unroll
        for (int u = -3; u <= 3; u++) {
            int xc = min(max(x + u, 0), 127);
            a += GW[u + 3] * s_in[lr7 + xc];
        }
        s_h[i] = a;
    }
    __syncthreads();
    for (int i = threadIdx.x; i < 32 * 128; i += 256) {
        int j = i >> 7, x = i & 127;
        float a = 0.f;
        #pragma unroll
        for (int u = -3; u <= 3; u++)
            a += GW[u + 3] * s_h[((j + 3 + u) << 7) + x];
        out[i] = a;
    }
}

// ---- K2b: flow decode + 7x7 blur (strip) * rain --------------------------
__global__ void __launch_bounds__(256) k_blurFlow() {
    __shared__ float s_in[38 * 128];
    __shared__ float s_h [38 * 128];
    int img  = blockIdx.x >> 2;          // 0..31 (0-15 fx, 16-31 fy)
    int s    = blockIdx.x & 3;
    int rbase = 32 * s - 3;
    float* out = g_flowb + img * IMG + 32 * s * 128;
    int gi0 = (img & 15) * IMG;
    bool isY = (img >= 16);

    for (int i = threadIdx.x; i < 38 * 128; i += 256) {
        int lr = i >> 7;
        int gr = min(max(rbase + lr, 0), 127);
        int gidx = gi0 + (gr << 7) + (i & 127);
        unsigned idx = g_best[gidx] & 0xFFu;
        float rain = g_rain[gidx];
        int dyi = (int)(idx / 13u);
        int dxi = (int)idx - dyi * 13;
        s_in[i] = (isY ? (float)(dyi - 6) : (float)(dxi - 6)) * rain;
    }
    __syncthreads();
    for (int i = threadIdx.x; i < 38 * 128; i += 256) {
        int x = i & 127;
        int lr7 = i - x;
        float a = 0.f;
        #pragma unroll
        for (int u = -3; u <= 3; u++) {
            int xc = min(max(x + u, 0), 127);
            a += GW[u + 3] * s_in[lr7 + xc];
        }
        s_h[i] = a;
    }
    __syncthreads();
    const float* rimg = g_rain + gi0 + 32 * s * 128;
    for (int i = threadIdx.x; i < 32 * 128; i += 256) {
        int j = i >> 7, x = i & 127;
        float a = 0.f;
        #pragma unroll
        for (int u = -3; u <= 3; u++)
            a += GW[u + 3] * s_h[((j + 3 + u) << 7) + x];
        out[i] = a * rimg[i];
    }
}

// ---- h-pass specialized on compile-time segment base (kills predicates) ---
template<int HC0>
__device__ __forceinline__ void hpass_seg(const float* __restrict__ p,
                                          const float* __restrict__ cr,
                                          float* __restrict__ hT) {
    float w = 0.f;
    #pragma unroll
    for (int u = -10; u <= 10; u++) {
        if (HC0 + u >= 0 && HC0 + u < 128) {       // compile-time
            float d = p[u + 12] - cr[HC0 + u];
            w += d * d;
        }
    }
    #pragma unroll
    for (int k = 0; k < 32; k++) {
        hT[(HC0 + k) * TSTR] = w;
        if (k < 31) {
            if (HC0 + k + 11 < 128) {              // compile-time
                float d = p[k + 23] - cr[HC0 + k + 11];
                w += d * d;
            }
            if (HC0 + k - 10 >= 0) {               // compile-time
                float d = p[k + 2] - cr[HC0 + k - 10];
                w -= d * d;
            }
        }
    }
}

// ---------------- K1: patch cost + argmin (ping-pong hsumT) ---------------
// smem: s_curr[128][141] | hsumT buf0[128][148] (overlaid with s_prev[128][132]
//       during init) | hsumT buf1[128][148]. hsum global row r at local r+10;
//       pad rows local 0..9 and 138..147 zeroed in both buffers.
__global__ void __launch_bounds__(512) k_cost() {
    extern __shared__ float sm[];
    float* s_curr = sm;
    float* s_hs0  = sm + SW * CSTR;            // buffer 0 (aliases s_prev)
    float* s_hs1  = sm + SW * CSTR + SW * TSTR; // buffer 1
    float* s_prev = s_hs0;                     // alias (valid only until p extracted)

    int blk  = blockIdx.x;
    int b    = blk / 26;
    int r26  = blk - b * 26;
    int dyi  = r26 >> 1;
    int half = r26 & 1;
    int dy   = dyi - 6;
    int dx0  = half ? 7 : 0;
    int dx1  = half ? 13 : 7;
    int t    = threadIdx.x;

    const float* pb = g_pblur + b * IMG;
    const float* cb = g_pblur + NPIX + b * IMG;

    for (int i = t; i < IMG; i += 512) {
        int r = i >> 7, c = i & 127;
        s_prev[r * PSTR + c] = pb[i];
    }
    for (int i = t; i < SW * 140; i += 512) {
        int r = i / 140;
        int c = i - r * 140 - 6;                 // -6..133
        int rs = min(max(r + dy, 0), 127);
        int cs = min(max(c, 0), 127);
        s_curr[r * CSTR + (c + 6)] = cb[(rs << 7) + cs];
    }
    __syncthreads();

    const int seg = t >> 7;            // 0..3 (warp-uniform)
    const int hr  = t & 127;           // h-pass row
    const int hc0 = seg << 5;          // h-pass cols [hc0, hc0+32)
    const int col = t & 127;           // v-pass column
    const int r0  = seg << 5;          // v-pass rows [r0, r0+32)

    float p[56];
    {
        const float4* pv = reinterpret_cast<const float4*>(s_prev + hr * PSTR + hc0 - 12);
        #pragma unroll
        for (int j = 0; j < 14; j++) {
            float4 q = pv[j];
            p[4*j] = q.x; p[4*j+1] = q.y; p[4*j+2] = q.z; p[4*j+3] = q.w;
        }
    }
    __syncthreads();   // all p extracted before hsumT buffers are written

    // zero pad rows (local 0..9 = global -10..-1; local 138..147 = 128..137), both buffers
    for (int i = t; i < 20 * SW; i += 512) {
        int row = i >> 7;
        int lr = (row < 10) ? row : (row + 128);
        s_hs0[(i & 127) * TSTR + lr] = 0.f;
        s_hs1[(i & 127) * TSTR + lr] = 0.f;
    }

    unsigned kmin[32];
    #pragma unroll
    for (int k = 0; k < 32; k++) kmin[k] = 0xFFFFFFFFu;

    #pragma unroll 1
    for (int dxi = dx0; dxi < dx1; dxi++) {
        int dx = dxi - 6;
        float* hbuf = (dxi & 1) ? s_hs1 : s_hs0;
        {
            const float* cr = s_curr + hr * CSTR + 6 + dx;
            float* hT = hbuf + hr + 10;
            switch (seg) {
                case 0:  hpass_seg<0> (p, cr, hT); break;
                case 1:  hpass_seg<32>(p, cr, hT); break;
                case 2:  hpass_seg<64>(p, cr, hT); break;
                default: hpass_seg<96>(p, cr, hT); break;
            }
        }
        __syncthreads();   // single barrier per dxi (ping-pong removes the other)
        {
            unsigned idx = (unsigned)(dyi * 13 + dxi);
            // chunk 0: outputs r0..r0+15 ; window rows r0-10..r0+25 = local r0..r0+35
            {
                float v[36];
                const float4* hv = reinterpret_cast<const float4*>(hbuf + col * TSTR + r0);
                #pragma unroll
                for (int j = 0; j < 9; j++) {
                    float4 q = hv[j];
                    v[4*j] = q.x; v[4*j+1] = q.y; v[4*j+2] = q.z; v[4*j+3] = q.w;
                }
                float w = 0.f;
                #pragma unroll
                for (int j = 0; j < 21; j++) w += v[j];
                #pragma unroll
                for (int k = 0; k < 16; k++) {
                    unsigned key = (__float_as_uint(w) & 0xFFFFFF00u) | idx;
                    kmin[k] = min(kmin[k], key);
                    if (k < 15) w += (v[k + 21] - v[k]);   // delta off-chain
                }
            }
            // chunk 1: outputs r0+16..r0+31 ; window rows r0+6..r0+41 = local r0+16..r0+51
            {
                float v[36];
                const float4* hv = reinterpret_cast<const float4*>(hbuf + col * TSTR + r0 + 16);
                #pragma unroll
                for (int j = 0; j < 9; j++) {
                    float4 q = hv[j];
                    v[4*j] = q.x; v[4*j+1] = q.y; v[4*j+2] = q.z; v[4*j+3] = q.w;
                }
                float w = 0.f;
                #pragma unroll
                for (int j = 0; j < 21; j++) w += v[j];
                #pragma unroll
                for (int k = 0; k < 16; k++) {
                    unsigned key = (__float_as_uint(w) & 0xFFFFFF00u) | idx;
                    kmin[16 + k] = min(kmin[16 + k], key);
                    if (k < 15) w += (v[k + 21] - v[k]);
                }
            }
        }
        // no second barrier: next h-pass writes the OTHER buffer; program order
        // guarantees v(dx-1) readers of that buffer passed the previous barrier.
    }
    unsigned* gb = g_best + b * IMG;
    #pragma unroll
    for (int k = 0; k < 32; k++)
        atomicMin(gb + ((r0 + k) << 7) + col, kmin[k]);
}

// ---- K3: loss with smem-staged flow rows + fused final reduction ----------
__global__ void __launch_bounds__(256) k_loss(const float* __restrict__ pred,
                                              const float* __restrict__ target,
                                              const float* __restrict__ ref,
                                              float* __restrict__ out) {
    __shared__ float s_fx[3 * 128];
    __shared__ float s_fy[3 * 128];

    int blk = blockIdx.x;              // 0..4095
    int b   = blk >> 8;                // 256 blocks per image
    int oy0 = (blk & 255) << 1;        // first of 2 rows

    float syb = 0.25f * ((float)oy0 + 0.5f) - 0.5f; syb = fmaxf(syb, 0.f);
    int R = min((int)syb, 127);
    const float* fxp = g_flowb + b * IMG;
    const float* fyp = g_flowb + NPIX + b * IMG;
    for (int i = threadIdx.x; i < 3 * 128; i += 256) {
        int r = min(R + (i >> 7), 127);
        int o = (r << 7) + (i & 127);
        s_fx[i] = fxp[o];
        s_fy[i] = fyp[o];
    }
    __syncthreads();

    int oy  = oy0 + (threadIdx.x >> 7);
    int ox0 = (threadIdx.x & 127) << 2;
    int pix0 = (b << 18) + (oy << 9) + ox0;

    float4 pv  = *reinterpret_cast<const float4*>(pred   + pix0);
    float4 tv4 = *reinterpret_cast<const float4*>(target + pix0);
    const float pr4[4] = {pv.x, pv.y, pv.z, pv.w};
    const float tg4[4] = {tv4.x, tv4.y, tv4.z, tv4.w};

    float sy = 0.25f * ((float)oy + 0.5f) - 0.5f; sy = fmaxf(sy, 0.f);
    int iy0 = (int)sy; float wy = sy - (float)iy0;
    int ly0 = iy0 - R;
    int ly1 = min(iy0 + 1, 127) - R;
    const float* rb = ref + b * (FW * FW);

    float acc = 0.f;
    #pragma unroll
    for (int j = 0; j < 4; j++) {
        int ox = ox0 + j;
        float sx = 0.25f * ((float)ox + 0.5f) - 0.5f; sx = fmaxf(sx, 0.f);
        int ix0 = (int)sx; float wx = sx - (float)ix0; int ix1 = min(ix0 + 1, 127);
        int o00 = (ly0 << 7) + ix0, o01 = (ly0 << 7) + ix1;
        int o10 = (ly1 << 7) + ix0, o11 = (ly1 << 7) + ix1;
        float w00 = (1.f - wy) * (1.f - wx), w01 = (1.f - wy) * wx;
        float w10 = wy * (1.f - wx),        w11 = wy * wx;
        float fx = (s_fx[o00]*w00 + s_fx[o01]*w01 + s_fx[o10]*w10 + s_fx[o11]*w11) * 4.0f;
        float fy = (s_fy[o00]*w00 + s_fy[o01]*w01 + s_fy[o10]*w10 + s_fy[o11]*w11) * 4.0f;
        float X = fminf(fmaxf((float)ox - fx, 0.f), 511.f);
        float Y = fminf(fmaxf((float)oy - fy, 0.f), 511.f);
        int x0 = (int)X; float ax = X - (float)x0; int x1 = min(x0 + 1, 511);
        int y0 = (int)Y; float ay = Y - (float)y0; int y1 = min(y0 + 1, 511);
        float v00 = rb[y0 * FW + x0], v01 = rb[y0 * FW + x1];
        float v10 = rb[y1 * FW + x0], v11 = rb[y1 * FW + x1];
        float tv = v00 * (1.f - ay) * (1.f - ax) + v01 * (1.f - ay) * ax +
                   v10 * ay * (1.f - ax)         + v11 * ay * ax;
        float teacher = fmaxf(tv, 0.f);
        float d  = pr4[j] - teacher;
        float ad = fabsf(d);
        float l  = (ad < 0.2f) ? (0.5f * d * d) : (0.2f * (ad - 0.1f));
        float m  = (teacher > 0.05f || tg4[j] > 0.05f) ? 1.f : 0.f;
        acc += l * m;
    }
    __shared__ float sred[256];
    sred[threadIdx.x] = acc;
    __syncthreads();
    for (int s = 128; s > 0; s >>= 1) {
        if (threadIdx.x < s) sred[threadIdx.x] += sred[threadIdx.x + s];
        __syncthreads();
    }
    __shared__ unsigned isLast;
    if (threadIdx.x == 0) {
        g_partial[blockIdx.x] = sred[0];
        __threadfence();
        unsigned c = atomicAdd(&g_done, 1u);
        isLast = (c == gridDim.x - 1) ? 1u : 0u;
    }
    __syncthreads();
    if (isLast) {
        __threadfence();
        float a = 0.f;
        for (int j2 = threadIdx.x; j2 < 4096; j2 += 256) a += g_partial[j2];
        sred[threadIdx.x] = a;
        __syncthreads();
        for (int s = 128; s > 0; s >>= 1) {
            if (threadIdx.x < s) sred[threadIdx.x] += sred[threadIdx.x + s];
            __syncthreads();
        }
        if (threadIdx.x == 0) {
            out[0] = sred[0] * (1.0f / 4194304.0f);
            g_done = 0;
        }
    }
}

// ---------------------------------------------------------------------------
extern "C" void kernel_launch(void* const* d_in, const int* in_sizes, int n_in,
                              void* d_out, int out_size) {
    const float* pred   = (const float*)d_in[0];
    const float* target = (const float*)d_in[1];
    const float* ref    = (const float*)d_in[2];
    float* out = (float*)d_out;

    const int costSmem = SW * (CSTR + 2 * TSTR) * (int)sizeof(float);   // 223744
    cudaFuncSetAttribute(k_cost, cudaFuncAttributeMaxDynamicSharedMemorySize, costSmem);

    k_blurPrep<<<128, 256>>>(target, ref);         // launch 0
    k_cost<<<NB * 13 * 2, 512, costSmem>>>();      // launch 1
    k_blurFlow<<<128, 256>>>();                    // launch 2
    k_loss<<<4096, 256>>>(pred, target, ref, out); // launch 3  <- profiler slot
}

// round 15
// speedup vs baseline: 1.0407x; 1.0407x over previous
#include <cuda_runtime.h>

#define NB   16
#define FW   512
#define SW   128
#define IMG  (SW*SW)        // 16384
#define NPIX (NB*IMG)       // 262144
#define CSTR 141            // s_curr stride (scalar conflict-free)
#define PSTR 132            // s_prev stride (float4 conflict-free, 4i pattern)
#define TSTR 156            // s_hsumT stride (float4 conflict-free: 156/4=39 odd)

// ---------------- device scratch (no cudaMalloc allowed) ----------------
__device__ float g_pblur[2*NPIX];
__device__ float g_rain [NPIX];
__device__ unsigned g_best[NPIX];    // packed (costbits & ~0xFF) | shiftIdx
__device__ float g_flowb[2*NPIX];
__device__ float g_partial[4096];
__device__ unsigned g_done;          // zero-init; reset by last block each run

__constant__ float GW[7] = {0.0044330482f, 0.0540055826f, 0.2420362293f,
                            0.3990502800f,
                            0.2420362293f, 0.0540055826f, 0.0044330482f};

// ---- K0: fused log1p-downsample + 7x7 blur + rain + best-init ------------
// block = (img 0..31, strip 0..7): 16-row strips, 22-row tiles with halo.
__global__ void __launch_bounds__(256) k_blurPrep(const float* __restrict__ target,
                                                  const float* __restrict__ ref) {
    __shared__ float s_in[22 * 128];
    __shared__ float s_h [22 * 128];
    int img  = blockIdx.x >> 3;
    int s    = blockIdx.x & 7;
    int rbase = 16 * s - 3;
    int b    = img & 15;
    bool isT = (img >= 16);
    const float* src = (isT ? target : ref) + b * (FW * FW);
    float* out = g_pblur + img * IMG + 16 * s * 128;

    for (int i = threadIdx.x; i < 22 * 128; i += 256) {
        int lr = i >> 7, x = i & 127;
        int gr = min(max(rbase + lr, 0), 127);
        int o = (4 * gr + 1) * FW + (4 * x + 1);
        float a0 = src[o], a1 = src[o + 1], a2 = src[o + FW], a3 = src[o + FW + 1];
        s_in[i] = 0.25f * (log1pf(fmaxf(a0, 0.f)) + log1pf(fmaxf(a1, 0.f)) +
                           log1pf(fmaxf(a2, 0.f)) + log1pf(fmaxf(a3, 0.f)));
        if (lr >= 3 && lr < 19) {             // owned rows: gr never clamped
            int gi = b * IMG + (gr << 7) + x;
            if (isT) {
                float tm = 0.25f * (a0 + a1 + a2 + a3);
                g_rain[gi] = (tm >= 0.1f) ? 1.0f : 0.0f;
            } else {
                g_best[gi] = 0xFFFFFFFFu;
            }
        }
    }
    __syncthreads();
    for (int i = threadIdx.x; i < 22 * 128; i += 256) {
        int x = i & 127;
        int lr7 = i - x;
        float a = 0.f;
        #pragma unroll
        for (int u = -3; u <= 3; u++) {
            int xc = min(max(x + u, 0), 127);
            a += GW[u + 3] * s_in[lr7 + xc];
        }
        s_h[i] = a;
    }
    __syncthreads();
    for (int i = threadIdx.x; i < 16 * 128; i += 256) {
        int j = i >> 7, x = i & 127;
        float a = 0.f;
        #pragma unroll
        for (int u = -3; u <= 3; u++)
            a += GW[u + 3] * s_h[((j + 3 + u) << 7) + x];
        out[i] = a;
    }
}

// ---- K2b: flow decode + 7x7 blur (16-row strips) * rain ------------------
__global__ void __launch_bounds__(256) k_blurFlow() {
    __shared__ float s_in[22 * 128];
    __shared__ float s_h [22 * 128];
    int img  = blockIdx.x >> 3;          // 0..31 (0-15 fx, 16-31 fy)
    int s    = blockIdx.x & 7;
    int rbase = 16 * s - 3;
    float* out = g_flowb + img * IMG + 16 * s * 128;
    int gi0 = (img & 15) * IMG;
    bool isY = (img >= 16);

    for (int i = threadIdx.x; i < 22 * 128; i += 256) {
        int lr = i >> 7;
        int gr = min(max(rbase + lr, 0), 127);
        int gidx = gi0 + (gr << 7) + (i & 127);
        unsigned idx = g_best[gidx] & 0xFFu;
        float rain = g_rain[gidx];
        int dyi = (int)(idx / 13u);
        int dxi = (int)idx - dyi * 13;
        s_in[i] = (isY ? (float)(dyi - 6) : (float)(dxi - 6)) * rain;
    }
    __syncthreads();
    for (int i = threadIdx.x; i < 22 * 128; i += 256) {
        int x = i & 127;
        int lr7 = i - x;
        float a = 0.f;
        #pragma unroll
        for (int u = -3; u <= 3; u++) {
            int xc = min(max(x + u, 0), 127);
            a += GW[u + 3] * s_in[lr7 + xc];
        }
        s_h[i] = a;
    }
    __syncthreads();
    const float* rimg = g_rain + gi0 + 16 * s * 128;
    for (int i = threadIdx.x; i < 16 * 128; i += 256) {
        int j = i >> 7, x = i & 127;
        float a = 0.f;
        #pragma unroll
        for (int u = -3; u <= 3; u++)
            a += GW[u + 3] * s_h[((j + 3 + u) << 7) + x];
        out[i] = a * rimg[i];
    }
}

// ---- h-pass specialized on compile-time segment base (kills predicates) ---
template<int HC0>
__device__ __forceinline__ void hpass_seg(const float* __restrict__ p,
                                          const float* __restrict__ cr,
                                          float* __restrict__ hT) {
    float w = 0.f;
    #pragma unroll
    for (int u = -10; u <= 10; u++) {
        if (HC0 + u >= 0 && HC0 + u < 128) {       // compile-time
            float d = p[u + 12] - cr[HC0 + u];
            w += d * d;
        }
    }
    #pragma unroll
    for (int k = 0; k < 32; k++) {
        hT[(HC0 + k) * TSTR] = w;
        if (k < 31) {
            if (HC0 + k + 11 < 128) {              // compile-time
                float d = p[k + 23] - cr[HC0 + k + 11];
                w += d * d;
            }
            if (HC0 + k - 10 >= 0) {               // compile-time
                float d = p[k + 2] - cr[HC0 + k - 10];
                w -= d * d;
            }
        }
    }
}

// ---------------- K1: patch cost + argmin (round-11 proven body) ----------
__global__ void __launch_bounds__(512) k_cost() {
    extern __shared__ float sm[];
    float* s_curr  = sm;
    float* s_hsumT = sm + SW * CSTR;   // overlaid with s_prev
    float* s_prev  = s_hsumT;          // alias (valid only until p extracted)

    int blk  = blockIdx.x;
    int b    = blk / 26;
    int r26  = blk - b * 26;
    int dyi  = r26 >> 1;
    int half = r26 & 1;
    int dy   = dyi - 6;
    int dx0  = half ? 7 : 0;
    int dx1  = half ? 13 : 7;
    int t    = threadIdx.x;

    const float* pb = g_pblur + b * IMG;
    const float* cb = g_pblur + NPIX + b * IMG;

    for (int i = t; i < IMG; i += 512) {
        int r = i >> 7, c = i & 127;
        s_prev[r * PSTR + c] = pb[i];
    }
    for (int i = t; i < SW * 140; i += 512) {
        int r = i / 140;
        int c = i - r * 140 - 6;                 // -6..133
        int rs = min(max(r + dy, 0), 127);
        int cs = min(max(c, 0), 127);
        s_curr[r * CSTR + (c + 6)] = cb[(rs << 7) + cs];
    }
    __syncthreads();

    const int seg = t >> 7;            // 0..3 (warp-uniform)
    const int hr  = t & 127;           // h-pass row
    const int hc0 = seg << 5;          // h-pass cols [hc0, hc0+32)
    const int col = t & 127;           // v-pass column
    const int r0  = seg << 5;          // v-pass rows [r0, r0+32)

    float p[56];
    {
        const float4* pv = reinterpret_cast<const float4*>(s_prev + hr * PSTR + hc0 - 12);
        #pragma unroll
        for (int j = 0; j < 14; j++) {
            float4 q = pv[j];
            p[4*j] = q.x; p[4*j+1] = q.y; p[4*j+2] = q.z; p[4*j+3] = q.w;
        }
    }
    __syncthreads();   // all p extracted before hsumT region is overwritten

    for (int i = t; i < 20 * SW; i += 512) {
        int row = i >> 7;
        int lr = (row < 10) ? (row + 4) : (row + 132);
        s_hsumT[(i & 127) * TSTR + lr] = 0.f;
    }

    unsigned kmin[32];
    #pragma unroll
    for (int k = 0; k < 32; k++) kmin[k] = 0xFFFFFFFFu;

    #pragma unroll 1
    for (int dxi = dx0; dxi < dx1; dxi++) {
        int dx = dxi - 6;
        {
            const float* cr = s_curr + hr * CSTR + 6 + dx;
            float* hT = s_hsumT + hr + 14;
            switch (seg) {
                case 0:  hpass_seg<0> (p, cr, hT); break;
                case 1:  hpass_seg<32>(p, cr, hT); break;
                case 2:  hpass_seg<64>(p, cr, hT); break;
                default: hpass_seg<96>(p, cr, hT); break;
            }
        }
        __syncthreads();
        {
            unsigned idx = (unsigned)(dyi * 13 + dxi);
            {
                float v[36];
                const float4* hv = reinterpret_cast<const float4*>(s_hsumT + col * TSTR + r0 + 4);
                #pragma unroll
                for (int j = 0; j < 9; j++) {
                    float4 q = hv[j];
                    v[4*j] = q.x; v[4*j+1] = q.y; v[4*j+2] = q.z; v[4*j+3] = q.w;
                }
                float w = 0.f;
                #pragma unroll
                for (int j = 0; j < 21; j++) w += v[j];
                #pragma unroll
                for (int k = 0; k < 16; k++) {
                    unsigned key = (__float_as_uint(w) & 0xFFFFFF00u) | idx;
                    kmin[k] = min(kmin[k], key);
                    if (k < 15) { w += v[k + 21]; w -= v[k]; }
                }
            }
            {
                float v[36];
                const float4* hv = reinterpret_cast<const float4*>(s_hsumT + col * TSTR + r0 + 20);
                #pragma unroll
                for (int j = 0; j < 9; j++) {
                    float4 q = hv[j];
                    v[4*j] = q.x; v[4*j+1] = q.y; v[4*j+2] = q.z; v[4*j+3] = q.w;
                }
                float w = 0.f;
                #pragma unroll
                for (int j = 0; j < 21; j++) w += v[j];
                #pragma unroll
                for (int k = 0; k < 16; k++) {
                    unsigned key = (__float_as_uint(w) & 0xFFFFFF00u) | idx;
                    kmin[16 + k] = min(kmin[16 + k], key);
                    if (k < 15) { w += v[k + 21]; w -= v[k]; }
                }
            }
        }
        __syncthreads();
    }
    unsigned* gb = g_best + b * IMG;
    #pragma unroll
    for (int k = 0; k < 32; k++)
        atomicMin(gb + ((r0 + k) << 7) + col, kmin[k]);
}

// ---- K3: loss with smem-staged flow rows + fused final reduction ----------
__global__ void __launch_bounds__(256) k_loss(const float* __restrict__ pred,
                                              const float* __restrict__ target,
                                              const float* __restrict__ ref,
                                              float* __restrict__ out) {
    __shared__ float s_fx[3 * 128];
    __shared__ float s_fy[3 * 128];

    int blk = blockIdx.x;              // 0..4095
    int b   = blk >> 8;                // 256 blocks per image
    int oy0 = (blk & 255) << 1;        // first of 2 rows

    float syb = 0.25f * ((float)oy0 + 0.5f) - 0.5f; syb = fmaxf(syb, 0.f);
    int R = min((int)syb, 127);
    const float* fxp = g_flowb + b * IMG;
    const float* fyp = g_flowb + NPIX + b * IMG;
    for (int i = threadIdx.x; i < 3 * 128; i += 256) {
        int r = min(R + (i >> 7), 127);
        int o = (r << 7) + (i & 127);
        s_fx[i] = fxp[o];
        s_fy[i] = fyp[o];
    }
    __syncthreads();

    int oy  = oy0 + (threadIdx.x >> 7);
    int ox0 = (threadIdx.x & 127) << 2;
    int pix0 = (b << 18) + (oy << 9) + ox0;

    float4 pv  = *reinterpret_cast<const float4*>(pred   + pix0);
    float4 tv4 = *reinterpret_cast<const float4*>(target + pix0);
    const float pr4[4] = {pv.x, pv.y, pv.z, pv.w};
    const float tg4[4] = {tv4.x, tv4.y, tv4.z, tv4.w};

    float sy = 0.25f * ((float)oy + 0.5f) - 0.5f; sy = fmaxf(sy, 0.f);
    int iy0 = (int)sy; float wy = sy - (float)iy0;
    int ly0 = iy0 - R;
    int ly1 = min(iy0 + 1, 127) - R;
    const float* rb = ref + b * (FW * FW);

    float acc = 0.f;
    #pragma unroll
    for (int j = 0; j < 4; j++) {
        int ox = ox0 + j;
        float sx = 0.25f * ((float)ox + 0.5f) - 0.5f; sx = fmaxf(sx, 0.f);
        int ix0 = (int)sx; float wx = sx - (float)ix0; int ix1 = min(ix0 + 1, 127);
        int o00 = (ly0 << 7) + ix0, o01 = (ly0 << 7) + ix1;
        int o10 = (ly1 << 7) + ix0, o11 = (ly1 << 7) + ix1;
        float w00 = (1.f - wy) * (1.f - wx), w01 = (1.f - wy) * wx;
        float w10 = wy * (1.f - wx),        w11 = wy * wx;
        float fx = (s_fx[o00]*w00 + s_fx[o01]*w01 + s_fx[o10]*w10 + s_fx[o11]*w11) * 4.0f;
        float fy = (s_fy[o00]*w00 + s_fy[o01]*w01 + s_fy[o10]*w10 + s_fy[o11]*w11) * 4.0f;
        float X = fminf(fmaxf((float)ox - fx, 0.f), 511.f);
        float Y = fminf(fmaxf((float)oy - fy, 0.f), 511.f);
        int x0 = (int)X; float ax = X - (float)x0; int x1 = min(x0 + 1, 511);
        int y0 = (int)Y; float ay = Y - (float)y0; int y1 = min(y0 + 1, 511);
        float v00 = rb[y0 * FW + x0], v01 = rb[y0 * FW + x1];
        float v10 = rb[y1 * FW + x0], v11 = rb[y1 * FW + x1];
        float tv = v00 * (1.f - ay) * (1.f - ax) + v01 * (1.f - ay) * ax +
                   v10 * ay * (1.f - ax)         + v11 * ay * ax;
        float teacher = fmaxf(tv, 0.f);
        float d  = pr4[j] - teacher;
        float ad = fabsf(d);
        float l  = (ad < 0.2f) ? (0.5f * d * d) : (0.2f * (ad - 0.1f));
        float m  = (teacher > 0.05f || tg4[j] > 0.05f) ? 1.f : 0.f;
        acc += l * m;
    }
    __shared__ float sred[256];
    sred[threadIdx.x] = acc;
    __syncthreads();
    for (int s = 128; s > 0; s >>= 1) {
        if (threadIdx.x < s) sred[threadIdx.x] += sred[threadIdx.x + s];
        __syncthreads();
    }
    __shared__ unsigned isLast;
    if (threadIdx.x == 0) {
        g_partial[blockIdx.x] = sred[0];
        __threadfence();
        unsigned c = atomicAdd(&g_done, 1u);
        isLast = (c == gridDim.x - 1) ? 1u : 0u;
    }
    __syncthreads();
    if (isLast) {
        __threadfence();
        float a = 0.f;
        for (int j2 = threadIdx.x; j2 < 4096; j2 += 256) a += g_partial[j2];
        sred[threadIdx.x] = a;
        __syncthreads();
        for (int s = 128; s > 0; s >>= 1) {
            if (threadIdx.x < s) sred[threadIdx.x] += sred[threadIdx.x + s];
            __syncthreads();
        }
        if (threadIdx.x == 0) {
            out[0] = sred[0] * (1.0f / 4194304.0f);
            g_done = 0;
        }
    }
}

// ---------------------------------------------------------------------------
extern "C" void kernel_launch(void* const* d_in, const int* in_sizes, int n_in,
                              void* d_out, int out_size) {
    const float* pred   = (const float*)d_in[0];
    const float* target = (const float*)d_in[1];
    const float* ref    = (const float*)d_in[2];
    float* out = (float*)d_out;

    const int costSmem = SW * (CSTR + TSTR) * (int)sizeof(float);   // 152064
    cudaFuncSetAttribute(k_cost, cudaFuncAttributeMaxDynamicSharedMemorySize, costSmem);

    k_blurPrep<<<256, 256>>>(target, ref);         // launch 0 (32 imgs x 8 strips)
    k_cost<<<NB * 13 * 2, 512, costSmem>>>();      // launch 1
    k_blurFlow<<<256, 256>>>();                    // launch 2 (32 imgs x 8 strips)
    k_loss<<<4096, 256>>>(pred, target, ref, out); // launch 3  <- profiler slot
}

// round 16
// speedup vs baseline: 1.1269x; 1.0829x over previous
#include <cuda_runtime.h>

#define NB   16
#define FW   512
#define SW   128
#define IMG  (SW*SW)        // 16384
#define NPIX (NB*IMG)       // 262144
#define CSTR 141            // s_curr stride (scalar conflict-free)
#define PSTR 132            // s_prev stride (float4 conflict-free, 4i pattern)
#define TSTR 156            // s_hsumT stride (float4 conflict-free: 156/4=39 odd)

// ---------------- device scratch (no cudaMalloc allowed) ----------------
__device__ float g_pblur[2*NPIX];
__device__ float g_rain [NPIX];
__device__ unsigned g_best[NPIX];    // packed (costbits & ~0xFF) | shiftIdx
__device__ float g_flowb[2*NPIX];
__device__ float g_partial[2048];
__device__ unsigned g_done;          // zero-init; reset by last block each run

__constant__ float GW[7] = {0.0044330482f, 0.0540055826f, 0.2420362293f,
                            0.3990502800f,
                            0.2420362293f, 0.0540055826f, 0.0044330482f};

// ---- K0: fused log1p-downsample + 7x7 blur + rain + best-init ------------
// block = (img 0..31, strip 0..7): 16-row strips, 22-row tiles with halo.
__global__ void __launch_bounds__(256) k_blurPrep(const float* __restrict__ target,
                                                  const float* __restrict__ ref) {
    __shared__ float s_in[22 * 128];
    __shared__ float s_h [22 * 128];
    int img  = blockIdx.x >> 3;
    int s    = blockIdx.x & 7;
    int rbase = 16 * s - 3;
    int b    = img & 15;
    bool isT = (img >= 16);
    const float* src = (isT ? target : ref) + b * (FW * FW);
    float* out = g_pblur + img * IMG + 16 * s * 128;

    for (int i = threadIdx.x; i < 22 * 128; i += 256) {
        int lr = i >> 7, x = i & 127;
        int gr = min(max(rbase + lr, 0), 127);
        int o = (4 * gr + 1) * FW + (4 * x + 1);
        float a0 = src[o], a1 = src[o + 1], a2 = src[o + FW], a3 = src[o + FW + 1];
        s_in[i] = 0.25f * (log1pf(fmaxf(a0, 0.f)) + log1pf(fmaxf(a1, 0.f)) +
                           log1pf(fmaxf(a2, 0.f)) + log1pf(fmaxf(a3, 0.f)));
        if (lr >= 3 && lr < 19) {             // owned rows: gr never clamped
            int gi = b * IMG + (gr << 7) + x;
            if (isT) {
                float tm = 0.25f * (a0 + a1 + a2 + a3);
                g_rain[gi] = (tm >= 0.1f) ? 1.0f : 0.0f;
            } else {
                g_best[gi] = 0xFFFFFFFFu;
            }
        }
    }
    __syncthreads();
    for (int i = threadIdx.x; i < 22 * 128; i += 256) {
        int x = i & 127;
        int lr7 = i - x;
        float a = 0.f;
        #pragma unroll
        for (int u = -3; u <= 3; u++) {
            int xc = min(max(x + u, 0), 127);
            a += GW[u + 3] * s_in[lr7 + xc];
        }
        s_h[i] = a;
    }
    __syncthreads();
    for (int i = threadIdx.x; i < 16 * 128; i += 256) {
        int j = i >> 7, x = i & 127;
        float a = 0.f;
        #pragma unroll
        for (int u = -3; u <= 3; u++)
            a += GW[u + 3] * s_h[((j + 3 + u) << 7) + x];
        out[i] = a;
    }
}

// ---- K2b: flow decode + 7x7 blur (16-row strips) * rain ------------------
__global__ void __launch_bounds__(256) k_blurFlow() {
    __shared__ float s_in[22 * 128];
    __shared__ float s_h [22 * 128];
    int img  = blockIdx.x >> 3;          // 0..31 (0-15 fx, 16-31 fy)
    int s    = blockIdx.x & 7;
    int rbase = 16 * s - 3;
    float* out = g_flowb + img * IMG + 16 * s * 128;
    int gi0 = (img & 15) * IMG;
    bool isY = (img >= 16);

    for (int i = threadIdx.x; i < 22 * 128; i += 256) {
        int lr = i >> 7;
        int gr = min(max(rbase + lr, 0), 127);
        int gidx = gi0 + (gr << 7) + (i & 127);
        unsigned idx = g_best[gidx] & 0xFFu;
        float rain = g_rain[gidx];
        int dyi = (int)(idx / 13u);
        int dxi = (int)idx - dyi * 13;
        s_in[i] = (isY ? (float)(dyi - 6) : (float)(dxi - 6)) * rain;
    }
    __syncthreads();
    for (int i = threadIdx.x; i < 22 * 128; i += 256) {
        int x = i & 127;
        int lr7 = i - x;
        float a = 0.f;
        #pragma unroll
        for (int u = -3; u <= 3; u++) {
            int xc = min(max(x + u, 0), 127);
            a += GW[u + 3] * s_in[lr7 + xc];
        }
        s_h[i] = a;
    }
    __syncthreads();
    const float* rimg = g_rain + gi0 + 16 * s * 128;
    for (int i = threadIdx.x; i < 16 * 128; i += 256) {
        int j = i >> 7, x = i & 127;
        float a = 0.f;
        #pragma unroll
        for (int u = -3; u <= 3; u++)
            a += GW[u + 3] * s_h[((j + 3 + u) << 7) + x];
        out[i] = a * rimg[i];
    }
}

// ---- h-pass specialized on compile-time segment base (kills predicates) ---
template<int HC0>
__device__ __forceinline__ void hpass_seg(const float* __restrict__ p,
                                          const float* __restrict__ cr,
                                          float* __restrict__ hT) {
    float w = 0.f;
    #pragma unroll
    for (int u = -10; u <= 10; u++) {
        if (HC0 + u >= 0 && HC0 + u < 128) {       // compile-time
            float d = p[u + 12] - cr[HC0 + u];
            w += d * d;
        }
    }
    #pragma unroll
    for (int k = 0; k < 32; k++) {
        hT[(HC0 + k) * TSTR] = w;
        if (k < 31) {
            if (HC0 + k + 11 < 128) {              // compile-time
                float d = p[k + 23] - cr[HC0 + k + 11];
                w += d * d;
            }
            if (HC0 + k - 10 >= 0) {               // compile-time
                float d = p[k + 2] - cr[HC0 + k - 10];
                w -= d * d;
            }
        }
    }
}

// ---------------- K1: patch cost + argmin (round-11 proven body) ----------
// heavy-first bid remap: blocks 0..207 do dxi 0..6 (7 iters), 208..415 do 7..12 (6)
__global__ void __launch_bounds__(512) k_cost() {
    extern __shared__ float sm[];
    float* s_curr  = sm;
    float* s_hsumT = sm + SW * CSTR;   // overlaid with s_prev
    float* s_prev  = s_hsumT;          // alias (valid only until p extracted)

    int blk  = blockIdx.x;
    int half = (blk >= 208) ? 1 : 0;
    int q    = blk - half * 208;
    int b    = q / 13;
    int dyi  = q - b * 13;
    int dy   = dyi - 6;
    int dx0  = half ? 7 : 0;
    int dx1  = half ? 13 : 7;
    int t    = threadIdx.x;

    const float* pb = g_pblur + b * IMG;
    const float* cb = g_pblur + NPIX + b * IMG;

    for (int i = t; i < IMG; i += 512) {
        int r = i >> 7, c = i & 127;
        s_prev[r * PSTR + c] = pb[i];
    }
    for (int i = t; i < SW * 140; i += 512) {
        int r = i / 140;
        int c = i - r * 140 - 6;                 // -6..133
        int rs = min(max(r + dy, 0), 127);
        int cs = min(max(c, 0), 127);
        s_curr[r * CSTR + (c + 6)] = cb[(rs << 7) + cs];
    }
    __syncthreads();

    const int seg = t >> 7;            // 0..3 (warp-uniform)
    const int hr  = t & 127;           // h-pass row
    const int hc0 = seg << 5;          // h-pass cols [hc0, hc0+32)
    const int col = t & 127;           // v-pass column
    const int r0  = seg << 5;          // v-pass rows [r0, r0+32)

    float p[56];
    {
        const float4* pv = reinterpret_cast<const float4*>(s_prev + hr * PSTR + hc0 - 12);
        #pragma unroll
        for (int j = 0; j < 14; j++) {
            float4 q4 = pv[j];
            p[4*j] = q4.x; p[4*j+1] = q4.y; p[4*j+2] = q4.z; p[4*j+3] = q4.w;
        }
    }
    __syncthreads();   // all p extracted before hsumT region is overwritten

    for (int i = t; i < 20 * SW; i += 512) {
        int row = i >> 7;
        int lr = (row < 10) ? (row + 4) : (row + 132);
        s_hsumT[(i & 127) * TSTR + lr] = 0.f;
    }

    unsigned kmin[32];
    #pragma unroll
    for (int k = 0; k < 32; k++) kmin[k] = 0xFFFFFFFFu;

    #pragma unroll 1
    for (int dxi = dx0; dxi < dx1; dxi++) {
        int dx = dxi - 6;
        {
            const float* cr = s_curr + hr * CSTR + 6 + dx;
            float* hT = s_hsumT + hr + 14;
            switch (seg) {
                case 0:  hpass_seg<0> (p, cr, hT); break;
                case 1:  hpass_seg<32>(p, cr, hT); break;
                case 2:  hpass_seg<64>(p, cr, hT); break;
                default: hpass_seg<96>(p, cr, hT); break;
            }
        }
        __syncthreads();
        {
            unsigned idx = (unsigned)(dyi * 13 + dxi);
            {
                float v[36];
                const float4* hv = reinterpret_cast<const float4*>(s_hsumT + col * TSTR + r0 + 4);
                #pragma unroll
                for (int j = 0; j < 9; j++) {
                    float4 q4 = hv[j];
                    v[4*j] = q4.x; v[4*j+1] = q4.y; v[4*j+2] = q4.z; v[4*j+3] = q4.w;
                }
                float w = 0.f;
                #pragma unroll
                for (int j = 0; j < 21; j++) w += v[j];
                #pragma unroll
                for (int k = 0; k < 16; k++) {
                    unsigned key = (__float_as_uint(w) & 0xFFFFFF00u) | idx;
                    kmin[k] = min(kmin[k], key);
                    if (k < 15) { w += v[k + 21]; w -= v[k]; }
                }
            }
            {
                float v[36];
                const float4* hv = reinterpret_cast<const float4*>(s_hsumT + col * TSTR + r0 + 20);
                #pragma unroll
                for (int j = 0; j < 9; j++) {
                    float4 q4 = hv[j];
                    v[4*j] = q4.x; v[4*j+1] = q4.y; v[4*j+2] = q4.z; v[4*j+3] = q4.w;
                }
                float w = 0.f;
                #pragma unroll
                for (int j = 0; j < 21; j++) w += v[j];
                #pragma unroll
                for (int k = 0; k < 16; k++) {
                    unsigned key = (__float_as_uint(w) & 0xFFFFFF00u) | idx;
                    kmin[16 + k] = min(kmin[16 + k], key);
                    if (k < 15) { w += v[k + 21]; w -= v[k]; }
                }
            }
        }
        __syncthreads();
    }
    unsigned* gb = g_best + b * IMG;
    #pragma unroll
    for (int k = 0; k < 32; k++)
        atomicMin(gb + ((r0 + k) << 7) + col, kmin[k]);
}

// ---- K3: loss, 4 rows/block (512 thr), smem flow rows + fused final -------
__global__ void __launch_bounds__(512) k_loss(const float* __restrict__ pred,
                                              const float* __restrict__ target,
                                              const float* __restrict__ ref,
                                              float* __restrict__ out) {
    __shared__ float s_fx[3 * 128];
    __shared__ float s_fy[3 * 128];

    int blk = blockIdx.x;              // 0..2047
    int b   = blk >> 7;                // 128 blocks per image
    int oy0 = (blk & 127) << 2;        // first of 4 rows

    // flow-row base: rows R, R+1, R+2 (clamped) cover iy0/iy1 for oy0..oy0+3
    float syb = 0.25f * ((float)oy0 + 0.5f) - 0.5f; syb = fmaxf(syb, 0.f);
    int R = min((int)syb, 127);
    const float* fxp = g_flowb + b * IMG;
    const float* fyp = g_flowb + NPIX + b * IMG;
    for (int i = threadIdx.x; i < 3 * 128; i += 512) {
        int r = min(R + (i >> 7), 127);
        int o = (r << 7) + (i & 127);
        s_fx[i] = fxp[o];
        s_fy[i] = fyp[o];
    }
    __syncthreads();

    int oy  = oy0 + (threadIdx.x >> 7);
    int ox0 = (threadIdx.x & 127) << 2;
    int pix0 = (b << 18) + (oy << 9) + ox0;

    float4 pv  = *reinterpret_cast<const float4*>(pred   + pix0);
    float4 tv4 = *reinterpret_cast<const float4*>(target + pix0);
    const float pr4[4] = {pv.x, pv.y, pv.z, pv.w};
    const float tg4[4] = {tv4.x, tv4.y, tv4.z, tv4.w};

    float sy = 0.25f * ((float)oy + 0.5f) - 0.5f; sy = fmaxf(sy, 0.f);
    int iy0 = (int)sy; float wy = sy - (float)iy0;
    int ly0 = iy0 - R;
    int ly1 = min(iy0 + 1, 127) - R;
    const float* rb = ref + b * (FW * FW);

    float acc = 0.f;
    #pragma unroll
    for (int j = 0; j < 4; j++) {
        int ox = ox0 + j;
        float sx = 0.25f * ((float)ox + 0.5f) - 0.5f; sx = fmaxf(sx, 0.f);
        int ix0 = (int)sx; float wx = sx - (float)ix0; int ix1 = min(ix0 + 1, 127);
        int o00 = (ly0 << 7) + ix0, o01 = (ly0 << 7) + ix1;
        int o10 = (ly1 << 7) + ix0, o11 = (ly1 << 7) + ix1;
        float w00 = (1.f - wy) * (1.f - wx), w01 = (1.f - wy) * wx;
        float w10 = wy * (1.f - wx),        w11 = wy * wx;
        float fx = (s_fx[o00]*w00 + s_fx[o01]*w01 + s_fx[o10]*w10 + s_fx[o11]*w11) * 4.0f;
        float fy = (s_fy[o00]*w00 + s_fy[o01]*w01 + s_fy[o10]*w10 + s_fy[o11]*w11) * 4.0f;
        float X = fminf(fmaxf((float)ox - fx, 0.f), 511.f);
        float Y = fminf(fmaxf((float)oy - fy, 0.f), 511.f);
        int x0 = (int)X; float ax = X - (float)x0; int x1 = min(x0 + 1, 511);
        int y0 = (int)Y; float ay = Y - (float)y0; int y1 = min(y0 + 1, 511);
        float v00 = rb[y0 * FW + x0], v01 = rb[y0 * FW + x1];
        float v10 = rb[y1 * FW + x0], v11 = rb[y1 * FW + x1];
        float tv = v00 * (1.f - ay) * (1.f - ax) + v01 * (1.f - ay) * ax +
                   v10 * ay * (1.f - ax)         + v11 * ay * ax;
        float teacher = fmaxf(tv, 0.f);
        float d  = pr4[j] - teacher;
        float ad = fabsf(d);
        float l  = (ad < 0.2f) ? (0.5f * d * d) : (0.2f * (ad - 0.1f));
        float m  = (teacher > 0.05f || tg4[j] > 0.05f) ? 1.f : 0.f;
        acc += l * m;
    }
    __shared__ float sred[512];
    sred[threadIdx.x] = acc;
    __syncthreads();
    for (int s = 256; s > 0; s >>= 1) {
        if (threadIdx.x < s) sred[threadIdx.x] += sred[threadIdx.x + s];
        __syncthreads();
    }
    __shared__ unsigned isLast;
    if (threadIdx.x == 0) {
        g_partial[blockIdx.x] = sred[0];
        __threadfence();
        unsigned c = atomicAdd(&g_done, 1u);
        isLast = (c == gridDim.x - 1) ? 1u : 0u;
    }
    __syncthreads();
    if (isLast) {
        __threadfence();
        float a = 0.f;
        for (int j2 = threadIdx.x; j2 < 2048; j2 += 512) a += g_partial[j2];
        sred[threadIdx.x] = a;
        __syncthreads();
        for (int s = 256; s > 0; s >>= 1) {
            if (threadIdx.x < s) sred[threadIdx.x] += sred[threadIdx.x + s];
            __syncthreads();
        }
        if (threadIdx.x == 0) {
            out[0] = sred[0] * (1.0f / 4194304.0f);
            g_done = 0;
        }
    }
}

// ---------------------------------------------------------------------------
extern "C" void kernel_launch(void* const* d_in, const int* in_sizes, int n_in,
                              void* d_out, int out_size) {
    const float* pred   = (const float*)d_in[0];
    const float* target = (const float*)d_in[1];
    const float* ref    = (const float*)d_in[2];
    float* out = (float*)d_out;

    const int costSmem = SW * (CSTR + TSTR) * (int)sizeof(float);   // 152064
    cudaFuncSetAttribute(k_cost, cudaFuncAttributeMaxDynamicSharedMemorySize, costSmem);

    k_blurPrep<<<256, 256>>>(target, ref);         // launch 0 (32 imgs x 8 strips)
    k_cost<<<NB * 13 * 2, 512, costSmem>>>();      // launch 1 (heavy-first order)
    k_blurFlow<<<256, 256>>>();                    // launch 2 (32 imgs x 8 strips)
    k_loss<<<2048, 512>>>(pred, target, ref, out); // launch 3  <- profiler slot
}

// round 17
// speedup vs baseline: 1.1273x; 1.0003x over previous
#include <cuda_runtime.h>

#define NB   16
#define FW   512
#define SW   128
#define IMG  (SW*SW)        // 16384
#define NPIX (NB*IMG)       // 262144
#define CSTR 141            // s_curr stride (scalar conflict-free)
#define PSTR 132            // s_prev stride (float4 conflict-free, 4i pattern)
#define TSTR 156            // s_hsumT stride (float4 conflict-free: 156/4=39 odd)

// ---------------- device scratch (no cudaMalloc allowed) ----------------
__device__ float g_pblur[2*NPIX];
__device__ float g_rain [NPIX];
__device__ unsigned g_best[NPIX];    // packed (costbits & ~0xFF) | shiftIdx
__device__ float g_flowb[2*NPIX];
__device__ float g_partial[1024];
__device__ unsigned g_done;          // zero-init; reset by last block each run

__constant__ float GW[7] = {0.0044330482f, 0.0540055826f, 0.2420362293f,
                            0.3990502800f,
                            0.2420362293f, 0.0540055826f, 0.0044330482f};

// ---- K0: fused log1p-downsample + 7x7 blur + rain + best-init ------------
// block = (img 0..31, strip 0..7): 16-row strips, 22-row tiles with halo.
__global__ void __launch_bounds__(256) k_blurPrep(const float* __restrict__ target,
                                                  const float* __restrict__ ref) {
    __shared__ float s_in[22 * 128];
    __shared__ float s_h [22 * 128];
    int img  = blockIdx.x >> 3;
    int s    = blockIdx.x & 7;
    int rbase = 16 * s - 3;
    int b    = img & 15;
    bool isT = (img >= 16);
    const float* src = (isT ? target : ref) + b * (FW * FW);
    float* out = g_pblur + img * IMG + 16 * s * 128;

    for (int i = threadIdx.x; i < 22 * 128; i += 256) {
        int lr = i >> 7, x = i & 127;
        int gr = min(max(rbase + lr, 0), 127);
        int o = (4 * gr + 1) * FW + (4 * x + 1);
        float a0 = src[o], a1 = src[o + 1], a2 = src[o + FW], a3 = src[o + FW + 1];
        s_in[i] = 0.25f * (log1pf(fmaxf(a0, 0.f)) + log1pf(fmaxf(a1, 0.f)) +
                           log1pf(fmaxf(a2, 0.f)) + log1pf(fmaxf(a3, 0.f)));
        if (lr >= 3 && lr < 19) {             // owned rows: gr never clamped
            int gi = b * IMG + (gr << 7) + x;
            if (isT) {
                float tm = 0.25f * (a0 + a1 + a2 + a3);
                g_rain[gi] = (tm >= 0.1f) ? 1.0f : 0.0f;
            } else {
                g_best[gi] = 0xFFFFFFFFu;
            }
        }
    }
    __syncthreads();
    for (int i = threadIdx.x; i < 22 * 128; i += 256) {
        int x = i & 127;
        int lr7 = i - x;
        float a = 0.f;
        #pragma unroll
        for (int u = -3; u <= 3; u++) {
            int xc = min(max(x + u, 0), 127);
            a += GW[u + 3] * s_in[lr7 + xc];
        }
        s_h[i] = a;
    }
    __syncthreads();
    for (int i = threadIdx.x; i < 16 * 128; i += 256) {
        int j = i >> 7, x = i & 127;
        float a = 0.f;
        #pragma unroll
        for (int u = -3; u <= 3; u++)
            a += GW[u + 3] * s_h[((j + 3 + u) << 7) + x];
        out[i] = a;
    }
}

// ---- K2b: flow decode + 7x7 blur (16-row strips) * rain ------------------
__global__ void __launch_bounds__(256) k_blurFlow() {
    __shared__ float s_in[22 * 128];
    __shared__ float s_h [22 * 128];
    int img  = blockIdx.x >> 3;          // 0..31 (0-15 fx, 16-31 fy)
    int s    = blockIdx.x & 7;
    int rbase = 16 * s - 3;
    float* out = g_flowb + img * IMG + 16 * s * 128;
    int gi0 = (img & 15) * IMG;
    bool isY = (img >= 16);

    for (int i = threadIdx.x; i < 22 * 128; i += 256) {
        int lr = i >> 7;
        int gr = min(max(rbase + lr, 0), 127);
        int gidx = gi0 + (gr << 7) + (i & 127);
        unsigned idx = g_best[gidx] & 0xFFu;
        float rain = g_rain[gidx];
        int dyi = (int)(idx / 13u);
        int dxi = (int)idx - dyi * 13;
        s_in[i] = (isY ? (float)(dyi - 6) : (float)(dxi - 6)) * rain;
    }
    __syncthreads();
    for (int i = threadIdx.x; i < 22 * 128; i += 256) {
        int x = i & 127;
        int lr7 = i - x;
        float a = 0.f;
        #pragma unroll
        for (int u = -3; u <= 3; u++) {
            int xc = min(max(x + u, 0), 127);
            a += GW[u + 3] * s_in[lr7 + xc];
        }
        s_h[i] = a;
    }
    __syncthreads();
    const float* rimg = g_rain + gi0 + 16 * s * 128;
    for (int i = threadIdx.x; i < 16 * 128; i += 256) {
        int j = i >> 7, x = i & 127;
        float a = 0.f;
        #pragma unroll
        for (int u = -3; u <= 3; u++)
            a += GW[u + 3] * s_h[((j + 3 + u) << 7) + x];
        out[i] = a * rimg[i];
    }
}

// ---- h-pass specialized on compile-time segment base (kills predicates) ---
template<int HC0>
__device__ __forceinline__ void hpass_seg(const float* __restrict__ p,
                                          const float* __restrict__ cr,
                                          float* __restrict__ hT) {
    float w = 0.f;
    #pragma unroll
    for (int u = -10; u <= 10; u++) {
        if (HC0 + u >= 0 && HC0 + u < 128) {       // compile-time
            float d = p[u + 12] - cr[HC0 + u];
            w += d * d;
        }
    }
    #pragma unroll
    for (int k = 0; k < 32; k++) {
        hT[(HC0 + k) * TSTR] = w;
        if (k < 31) {
            if (HC0 + k + 11 < 128) {              // compile-time
                float d = p[k + 23] - cr[HC0 + k + 11];
                w += d * d;
            }
            if (HC0 + k - 10 >= 0) {               // compile-time
                float d = p[k + 2] - cr[HC0 + k - 10];
                w -= d * d;
            }
        }
    }
}

// ---------------- K1: patch cost + argmin (round-11 proven body) ----------
// heavy-first bid remap: blocks 0..207 do dxi 0..6 (7 iters), 208..415 do 7..12 (6)
__global__ void __launch_bounds__(512) k_cost() {
    extern __shared__ float sm[];
    float* s_curr  = sm;
    float* s_hsumT = sm + SW * CSTR;   // overlaid with s_prev
    float* s_prev  = s_hsumT;          // alias (valid only until p extracted)

    int blk  = blockIdx.x;
    int half = (blk >= 208) ? 1 : 0;
    int q    = blk - half * 208;
    int b    = q / 13;
    int dyi  = q - b * 13;
    int dy   = dyi - 6;
    int dx0  = half ? 7 : 0;
    int dx1  = half ? 13 : 7;
    int t    = threadIdx.x;

    const float* pb = g_pblur + b * IMG;
    const float* cb = g_pblur + NPIX + b * IMG;

    for (int i = t; i < IMG; i += 512) {
        int r = i >> 7, c = i & 127;
        s_prev[r * PSTR + c] = pb[i];
    }
    for (int i = t; i < SW * 140; i += 512) {
        int r = i / 140;
        int c = i - r * 140 - 6;                 // -6..133
        int rs = min(max(r + dy, 0), 127);
        int cs = min(max(c, 0), 127);
        s_curr[r * CSTR + (c + 6)] = cb[(rs << 7) + cs];
    }
    __syncthreads();

    const int seg = t >> 7;            // 0..3 (warp-uniform)
    const int hr  = t & 127;           // h-pass row
    const int hc0 = seg << 5;          // h-pass cols [hc0, hc0+32)
    const int col = t & 127;           // v-pass column
    const int r0  = seg << 5;          // v-pass rows [r0, r0+32)

    float p[56];
    {
        const float4* pv = reinterpret_cast<const float4*>(s_prev + hr * PSTR + hc0 - 12);
        #pragma unroll
        for (int j = 0; j < 14; j++) {
            float4 q4 = pv[j];
            p[4*j] = q4.x; p[4*j+1] = q4.y; p[4*j+2] = q4.z; p[4*j+3] = q4.w;
        }
    }
    __syncthreads();   // all p extracted before hsumT region is overwritten

    for (int i = t; i < 20 * SW; i += 512) {
        int row = i >> 7;
        int lr = (row < 10) ? (row + 4) : (row + 132);
        s_hsumT[(i & 127) * TSTR + lr] = 0.f;
    }

    unsigned kmin[32];
    #pragma unroll
    for (int k = 0; k < 32; k++) kmin[k] = 0xFFFFFFFFu;

    #pragma unroll 1
    for (int dxi = dx0; dxi < dx1; dxi++) {
        int dx = dxi - 6;
        {
            const float* cr = s_curr + hr * CSTR + 6 + dx;
            float* hT = s_hsumT + hr + 14;
            switch (seg) {
                case 0:  hpass_seg<0> (p, cr, hT); break;
                case 1:  hpass_seg<32>(p, cr, hT); break;
                case 2:  hpass_seg<64>(p, cr, hT); break;
                default: hpass_seg<96>(p, cr, hT); break;
            }
        }
        __syncthreads();
        {
            unsigned idx = (unsigned)(dyi * 13 + dxi);
            {
                float v[36];
                const float4* hv = reinterpret_cast<const float4*>(s_hsumT + col * TSTR + r0 + 4);
                #pragma unroll
                for (int j = 0; j < 9; j++) {
                    float4 q4 = hv[j];
                    v[4*j] = q4.x; v[4*j+1] = q4.y; v[4*j+2] = q4.z; v[4*j+3] = q4.w;
                }
                float w = 0.f;
                #pragma unroll
                for (int j = 0; j < 21; j++) w += v[j];
                #pragma unroll
                for (int k = 0; k < 16; k++) {
                    unsigned key = (__float_as_uint(w) & 0xFFFFFF00u) | idx;
                    kmin[k] = min(kmin[k], key);
                    if (k < 15) { w += v[k + 21]; w -= v[k]; }
                }
            }
            {
                float v[36];
                const float4* hv = reinterpret_cast<const float4*>(s_hsumT + col * TSTR + r0 + 20);
                #pragma unroll
                for (int j = 0; j < 9; j++) {
                    float4 q4 = hv[j];
                    v[4*j] = q4.x; v[4*j+1] = q4.y; v[4*j+2] = q4.z; v[4*j+3] = q4.w;
                }
                float w = 0.f;
                #pragma unroll
                for (int j = 0; j < 21; j++) w += v[j];
                #pragma unroll
                for (int k = 0; k < 16; k++) {
                    unsigned key = (__float_as_uint(w) & 0xFFFFFF00u) | idx;
                    kmin[16 + k] = min(kmin[16 + k], key);
                    if (k < 15) { w += v[k + 21]; w -= v[k]; }
                }
            }
        }
        __syncthreads();
    }
    unsigned* gb = g_best + b * IMG;
    #pragma unroll
    for (int k = 0; k < 32; k++)
        atomicMin(gb + ((r0 + k) << 7) + col, kmin[k]);
}

// ---- K3: loss, 8 rows/block (1024 thr), smem flow rows + fused final ------
__global__ void __launch_bounds__(1024) k_loss(const float* __restrict__ pred,
                                               const float* __restrict__ target,
                                               const float* __restrict__ ref,
                                               float* __restrict__ out) {
    __shared__ float s_fx[4 * 128];
    __shared__ float s_fy[4 * 128];

    int blk = blockIdx.x;              // 0..1023
    int b   = blk >> 6;                // 64 blocks per image
    int oy0 = (blk & 63) << 3;         // first of 8 rows

    // flow rows R..R+3 (clamped) cover iy0/iy1 for oy0..oy0+7 (sy span 1.75)
    float syb = 0.25f * ((float)oy0 + 0.5f) - 0.5f; syb = fmaxf(syb, 0.f);
    int R = min((int)syb, 127);
    const float* fxp = g_flowb + b * IMG;
    const float* fyp = g_flowb + NPIX + b * IMG;
    for (int i = threadIdx.x; i < 4 * 128; i += 1024) {
        int r = min(R + (i >> 7), 127);
        int o = (r << 7) + (i & 127);
        s_fx[i] = fxp[o];
        s_fy[i] = fyp[o];
    }
    __syncthreads();

    int oy  = oy0 + (threadIdx.x >> 7);     // 8 rows
    int ox0 = (threadIdx.x & 127) << 2;
    int pix0 = (b << 18) + (oy << 9) + ox0;

    float4 pv  = *reinterpret_cast<const float4*>(pred   + pix0);
    float4 tv4 = *reinterpret_cast<const float4*>(target + pix0);
    const float pr4[4] = {pv.x, pv.y, pv.z, pv.w};
    const float tg4[4] = {tv4.x, tv4.y, tv4.z, tv4.w};

    float sy = 0.25f * ((float)oy + 0.5f) - 0.5f; sy = fmaxf(sy, 0.f);
    int iy0 = (int)sy; float wy = sy - (float)iy0;
    int ly0 = iy0 - R;                       // 0..2
    int ly1 = min(iy0 + 1, 127) - R;         // 0..3
    const float* rb = ref + b * (FW * FW);

    float acc = 0.f;
    #pragma unroll
    for (int j = 0; j < 4; j++) {
        int ox = ox0 + j;
        float sx = 0.25f * ((float)ox + 0.5f) - 0.5f; sx = fmaxf(sx, 0.f);
        int ix0 = (int)sx; float wx = sx - (float)ix0; int ix1 = min(ix0 + 1, 127);
        int o00 = (ly0 << 7) + ix0, o01 = (ly0 << 7) + ix1;
        int o10 = (ly1 << 7) + ix0, o11 = (ly1 << 7) + ix1;
        float w00 = (1.f - wy) * (1.f - wx), w01 = (1.f - wy) * wx;
        float w10 = wy * (1.f - wx),        w11 = wy * wx;
        float fx = (s_fx[o00]*w00 + s_fx[o01]*w01 + s_fx[o10]*w10 + s_fx[o11]*w11) * 4.0f;
        float fy = (s_fy[o00]*w00 + s_fy[o01]*w01 + s_fy[o10]*w10 + s_fy[o11]*w11) * 4.0f;
        float X = fminf(fmaxf((float)ox - fx, 0.f), 511.f);
        float Y = fminf(fmaxf((float)oy - fy, 0.f), 511.f);
        int x0 = (int)X; float ax = X - (float)x0; int x1 = min(x0 + 1, 511);
        int y0 = (int)Y; float ay = Y - (float)y0; int y1 = min(y0 + 1, 511);
        float v00 = rb[y0 * FW + x0], v01 = rb[y0 * FW + x1];
        float v10 = rb[y1 * FW + x0], v11 = rb[y1 * FW + x1];
        float tv = v00 * (1.f - ay) * (1.f - ax) + v01 * (1.f - ay) * ax +
                   v10 * ay * (1.f - ax)         + v11 * ay * ax;
        float teacher = fmaxf(tv, 0.f);
        float d  = pr4[j] - teacher;
        float ad = fabsf(d);
        float l  = (ad < 0.2f) ? (0.5f * d * d) : (0.2f * (ad - 0.1f));
        float m  = (teacher > 0.05f || tg4[j] > 0.05f) ? 1.f : 0.f;
        acc += l * m;
    }
    __shared__ float sred[1024];
    sred[threadIdx.x] = acc;
    __syncthreads();
    for (int s = 512; s > 0; s >>= 1) {
        if (threadIdx.x < s) sred[threadIdx.x] += sred[threadIdx.x + s];
        __syncthreads();
    }
    __shared__ unsigned isLast;
    if (threadIdx.x == 0) {
        g_partial[blockIdx.x] = sred[0];
        __threadfence();
        unsigned c = atomicAdd(&g_done, 1u);
        isLast = (c == gridDim.x - 1) ? 1u : 0u;
    }
    __syncthreads();
    if (isLast) {
        __threadfence();
        sred[threadIdx.x] = g_partial[threadIdx.x];
        __syncthreads();
        for (int s = 512; s > 0; s >>= 1) {
            if (threadIdx.x < s) sred[threadIdx.x] += sred[threadIdx.x + s];
            __syncthreads();
        }
        if (threadIdx.x == 0) {
            out[0] = sred[0] * (1.0f / 4194304.0f);
            g_done = 0;
        }
    }
}

// ---------------------------------------------------------------------------
extern "C" void kernel_launch(void* const* d_in, const int* in_sizes, int n_in,
                              void* d_out, int out_size) {
    const float* pred   = (const float*)d_in[0];
    const float* target = (const float*)d_in[1];
    const float* ref    = (const float*)d_in[2];
    float* out = (float*)d_out;

    const int costSmem = SW * (CSTR + TSTR) * (int)sizeof(float);   // 152064
    cudaFuncSetAttribute(k_cost, cudaFuncAttributeMaxDynamicSharedMemorySize, costSmem);

    k_blurPrep<<<256, 256>>>(target, ref);          // launch 0 (32 imgs x 8 strips)
    k_cost<<<NB * 13 * 2, 512, costSmem>>>();       // launch 1 (heavy-first order)
    k_blurFlow<<<256, 256>>>();                     // launch 2 (32 imgs x 8 strips)
    k_loss<<<1024, 1024>>>(pred, target, ref, out); // launch 3  <- profiler slot
}